// round 8
// baseline (speedup 1.0000x reference)
#include <cuda_runtime.h>
#include <stdint.h>

#define EMB   1024
#define NH    16
#define HD    64
#define BATCH 4
#define SEQ   2048
#define MROWS (BATCH*SEQ)   // 8192
#define KDIM  EMB           // 1024

// ---------------- scratch (static __device__, allocation-guard safe) ----------
__device__ float g_q [(size_t)BATCH*NH*SEQ*HD];   // [B,H,S,D]
__device__ float g_k [(size_t)BATCH*NH*SEQ*HD];
__device__ float g_v [(size_t)BATCH*NH*SEQ*HD];
__device__ float g_ao[(size_t)MROWS*EMB];         // attention out, [B,S,E]

// ---------------- TF32 helpers -------------------------------------------------
__device__ __forceinline__ uint32_t f2tf32(float x) {
    uint32_t r;
    asm("cvt.rna.tf32.f32 %0, %1;" : "=r"(r) : "f"(x));
    return r;
}
__device__ __forceinline__ float f2tf32f(float x) {
    return __uint_as_float(f2tf32(x));
}

__device__ __forceinline__ void mma_tf32(float& d0, float& d1, float& d2, float& d3,
                                         uint32_t a0, uint32_t a1, uint32_t a2, uint32_t a3,
                                         uint32_t b0, uint32_t b1)
{
    asm volatile(
        "mma.sync.aligned.m16n8k8.row.col.f32.tf32.tf32.f32 "
        "{%0,%1,%2,%3}, {%4,%5,%6,%7}, {%8,%9}, {%0,%1,%2,%3};"
        : "+f"(d0), "+f"(d1), "+f"(d2), "+f"(d3)
        : "r"(a0), "r"(a1), "r"(a2), "r"(a3), "r"(b0), "r"(b1));
}

// ---------------- TF32 tensor-core GEMM (fragment-major smem) -------------------
// C[M,N] = A[M,K] @ W[N,K]^T.  Block tile 128x128x32, 8 warps (2x4), 64x32/warp.
//
// A-frag layout: AF[(kb*8+mb)*32 + lane][reg0..3]  (float4 per lane)
//   element (m,k): kb=k/8, mb=m/16, lane=(m%8)*4+(k%4), reg=((m%16)>>3)+2*((k%8)>>2)
// B-frag layout: BF[(kb*16+nb)*32 + lane][reg0..1] (float2 per lane)
//   element (n,k): kb=k/8, nb=n/8, lane=(n%8)*4+(k%4), reg=(k%8)>>2
#define BM 128
#define BN 128
#define BK 32
#define AF_FLOATS (4*8*32*4)    // 4096
#define BF_FLOATS (4*16*32*2)   // 4096

template<bool SPLIT>
__device__ __forceinline__ void gemm_body(const float* __restrict__ A,
                                          const float* __restrict__ W,
                                          float* __restrict__ C,
                                          float* __restrict__ AF,
                                          float* __restrict__ BF)
{
    const int tid    = threadIdx.x;
    const int lane   = tid & 31;
    const int warp   = tid >> 5;
    const int warp_m = warp >> 2;           // 0..1
    const int warp_n = warp & 3;            // 0..3
    const int m0     = blockIdx.y * BM;
    const int n0     = blockIdx.x * BN;

    // staging geometry (k-position fixed per thread)
    const int scol = (tid & 7) * 4;         // 0,4,..,28
    const int skb  = scol >> 3;             // 0..3
    const int sh   = (scol >> 2) & 1;       // 0/1

    float acc[4][4][4];
    #pragma unroll
    for (int i = 0; i < 4; i++)
        #pragma unroll
        for (int j = 0; j < 4; j++)
            #pragma unroll
            for (int c = 0; c < 4; c++) acc[i][j][c] = 0.f;

    float4 sa[4], sw[4];
    #pragma unroll
    for (int p = 0; p < 4; p++) {
        const int row = (tid >> 3) + p * 32;
        sa[p] = *(const float4*)(A + (size_t)(m0 + row) * KDIM + scol);
        sw[p] = *(const float4*)(W + (size_t)(n0 + row) * KDIM + scol);
    }

    for (int k0 = 0; k0 < KDIM; k0 += BK) {
        // ---- stage into fragment-major smem (with tf32 rounding) ----
        #pragma unroll
        for (int p = 0; p < 4; p++) {
            const int m  = (tid >> 3) + p * 32;
            const int mb = m >> 4;
            const int rl = (m >> 3) & 1;
            float* ap = &AF[(((skb * 8 + mb) * 32 + (m & 7) * 4) << 2) + rl + 2 * sh];
            ap[0]  = f2tf32f(sa[p].x);
            ap[4]  = f2tf32f(sa[p].y);
            ap[8]  = f2tf32f(sa[p].z);
            ap[12] = f2tf32f(sa[p].w);
            const int nb = m >> 3;
            float* bp = &BF[(((skb * 16 + nb) * 32 + (m & 7) * 4) << 1) + sh];
            bp[0] = f2tf32f(sw[p].x);
            bp[2] = f2tf32f(sw[p].y);
            bp[4] = f2tf32f(sw[p].z);
            bp[6] = f2tf32f(sw[p].w);
        }
        __syncthreads();

        // prefetch next K-slab
        if (k0 + BK < KDIM) {
            #pragma unroll
            for (int p = 0; p < 4; p++) {
                const int row = (tid >> 3) + p * 32;
                sa[p] = *(const float4*)(A + (size_t)(m0 + row) * KDIM + k0 + BK + scol);
                sw[p] = *(const float4*)(W + (size_t)(n0 + row) * KDIM + k0 + BK + scol);
            }
        }

        // ---- compute: vectorized fragment loads ----
        #pragma unroll
        for (int kb = 0; kb < 4; kb++) {
            float4 av[4];
            #pragma unroll
            for (int mi = 0; mi < 4; mi++)
                av[mi] = *(const float4*)&AF[(((kb * 8 + warp_m * 4 + mi) * 32 + lane) << 2)];
            float2 bv[4];
            #pragma unroll
            for (int ni = 0; ni < 4; ni++)
                bv[ni] = *(const float2*)&BF[(((kb * 16 + warp_n * 4 + ni) * 32 + lane) << 1)];
            #pragma unroll
            for (int mi = 0; mi < 4; mi++)
                #pragma unroll
                for (int ni = 0; ni < 4; ni++)
                    mma_tf32(acc[mi][ni][0], acc[mi][ni][1], acc[mi][ni][2], acc[mi][ni][3],
                             __float_as_uint(av[mi].x), __float_as_uint(av[mi].y),
                             __float_as_uint(av[mi].z), __float_as_uint(av[mi].w),
                             __float_as_uint(bv[ni].x), __float_as_uint(bv[ni].y));
        }
        __syncthreads();
    }

    // ---- epilogue ----
    const int grp = lane >> 2;
    const int tig = lane & 3;
    const int mw  = warp_m * 64;
    const int nw  = warp_n * 32;
    #pragma unroll
    for (int mi = 0; mi < 4; mi++) {
        #pragma unroll
        for (int ni = 0; ni < 4; ni++) {
            const int row = m0 + mw + mi * 16 + grp;
            const int col = n0 + nw + ni * 8 + 2 * tig;
            #pragma unroll
            for (int half = 0; half < 2; half++) {
                const int m = row + half * 8;
                const float v0 = acc[mi][ni][half * 2 + 0];
                const float v1 = acc[mi][ni][half * 2 + 1];
                size_t idx;
                if (SPLIT) {   // [B,H,S,D]
                    const int b = m >> 11, s = m & 2047, h = col >> 6, d = col & 63;
                    idx = ((size_t)(b * NH + h) * SEQ + s) * HD + d;
                } else {
                    idx = (size_t)m * EMB + col;
                }
                *(float2*)(C + idx) = make_float2(v0, v1);
            }
        }
    }
}

// fused QKV: gridDim.z = 3 selects weight/output
__global__ void __launch_bounds__(256)
qkv_gemm(const float* __restrict__ x,
         const float* __restrict__ wq, const float* __restrict__ wk,
         const float* __restrict__ wv,
         float* __restrict__ pq, float* __restrict__ pk, float* __restrict__ pv)
{
    __shared__ __align__(16) float AF[AF_FLOATS];
    __shared__ __align__(16) float BF[BF_FLOATS];
    const int z = blockIdx.z;
    const float* W = (z == 0) ? wq : (z == 1) ? wk : wv;
    float*       C = (z == 0) ? pq : (z == 1) ? pk : pv;
    gemm_body<true>(x, W, C, AF, BF);
}

__global__ void __launch_bounds__(256)
out_gemm(const float* __restrict__ A, const float* __restrict__ W,
         float* __restrict__ C)
{
    __shared__ __align__(16) float AF[AF_FLOATS];
    __shared__ __align__(16) float BF[BF_FLOATS];
    gemm_body<false>(A, W, C, AF, BF);
}

// ---------------- tensor-core causal flash attention ---------------------------
// CTA: 128 q-rows of one (b,h). 8 warps x 16 q-rows. KV tiles of 64.
// K staged in B-fragment layout: KF[(kb*8+nb)*32 + lane][reg0..1], kb,nb < 8.
#define KF_FLOATS (8*8*32*2)    // 4096
#define VSTR 72                 // V smem stride -> bank = (8*row + col) % 32
#define PSTR 68                 // P / Q staging stride

#define FLASH_SMEM_FLOATS (KF_FLOATS + 64*VSTR + 128*PSTR)
#define FLASH_SMEM_BYTES  (FLASH_SMEM_FLOATS*4 + 64*4)

__global__ void __launch_bounds__(256)
flash_tc(const float* __restrict__ Qg, const float* __restrict__ Kg,
         const float* __restrict__ Vg, const int* __restrict__ maskg,
         float* __restrict__ Og)
{
    extern __shared__ __align__(16) float sm[];
    float* KF = sm;                    // K fragments
    float* Vs = KF + KF_FLOATS;        // [64][VSTR]
    float* Ps = Vs + 64 * VSTR;        // [128][PSTR]  (Q staging, then P)
    int*   msk = (int*)(Ps + 128 * PSTR);

    const int bh   = blockIdx.x;
    const int b    = bh >> 4;
    const int h    = bh & 15;
    const int qt   = gridDim.y - 1 - blockIdx.y;   // heavy tiles first
    const int q0   = qt * 128;
    const int tid  = threadIdx.x;
    const int lane = tid & 31;
    const int warp = tid >> 5;
    const int grp  = lane >> 2;        // 0..7
    const int tig  = lane & 3;         // 0..3
    const int mw   = warp * 16;        // warp's q-row offset in tile

    const float qscale = 0.125f * 1.44269504088896f;  // 1/sqrt(64) * log2(e)

    // ---- stage Q tile [128 x 64] (scaled, tf32) into Ps, pull fragments -------
    #pragma unroll
    for (int p = 0; p < 8; p++) {
        const int idx = tid + p * 256;
        const int row = idx >> 4;
        const int col = (idx & 15) * 4;
        float4 t = *(const float4*)(Qg + ((size_t)bh * SEQ + q0 + row) * HD + col);
        float* dp = &Ps[row * PSTR + col];
        dp[0] = f2tf32f(t.x * qscale);
        dp[1] = f2tf32f(t.y * qscale);
        dp[2] = f2tf32f(t.z * qscale);
        dp[3] = f2tf32f(t.w * qscale);
    }
    __syncthreads();

    uint32_t qf[8][4];
    #pragma unroll
    for (int ks = 0; ks < 8; ks++) {
        const int k8 = ks * 8;
        qf[ks][0] = __float_as_uint(Ps[(mw + grp    ) * PSTR + k8 + tig    ]);
        qf[ks][1] = __float_as_uint(Ps[(mw + grp + 8) * PSTR + k8 + tig    ]);
        qf[ks][2] = __float_as_uint(Ps[(mw + grp    ) * PSTR + k8 + tig + 4]);
        qf[ks][3] = __float_as_uint(Ps[(mw + grp + 8) * PSTR + k8 + tig + 4]);
    }

    float o[8][4];
    #pragma unroll
    for (int nt = 0; nt < 8; nt++)
        #pragma unroll
        for (int c = 0; c < 4; c++) o[nt][c] = 0.f;
    float m0r = -1e30f, m1r = -1e30f, l0 = 0.f, l1 = 0.f;

    const int q_row0 = q0 + mw + grp;
    const int q_row1 = q_row0 + 8;
    const int* mrow  = maskg + b * SEQ;
    const int  ntile = 2 * qt + 2;     // causal: kv tiles 0 .. 2*qt+1

    // K staging geometry (fixed per thread)
    const int kcol = (tid & 15) * 4;   // 0..60
    const int kkb  = kcol >> 3;        // 0..7
    const int kh   = (kcol >> 2) & 1;

    for (int kt = 0; kt < ntile; kt++) {
        const int kv0 = kt * 64;
        __syncthreads();   // previous tile's KF/Vs reads (and P reads) complete

        // ---- load K (frag layout) + V (row layout) tiles + mask ----
        #pragma unroll
        for (int p = 0; p < 4; p++) {
            const int row = (tid >> 4) + p * 16;
            float4 tk = *(const float4*)(Kg + ((size_t)bh * SEQ + kv0 + row) * HD + kcol);
            float* kp = &KF[(((kkb * 8 + (row >> 3)) * 32 + (row & 7) * 4) << 1) + kh];
            kp[0] = f2tf32f(tk.x);
            kp[2] = f2tf32f(tk.y);
            kp[4] = f2tf32f(tk.z);
            kp[6] = f2tf32f(tk.w);
            float4 tv = *(const float4*)(Vg + ((size_t)bh * SEQ + kv0 + row) * HD + kcol);
            float* vp = &Vs[row * VSTR + kcol];
            vp[0] = f2tf32f(tv.x);
            vp[1] = f2tf32f(tv.y);
            vp[2] = f2tf32f(tv.z);
            vp[3] = f2tf32f(tv.w);
        }
        int mv = 1;
        if (tid < 64) { mv = mrow[kv0 + tid]; msk[tid] = mv; }
        const int allv = __syncthreads_and(mv != 0);   // barrier + all-reduce

        // ---- S = Q @ K^T ----
        float s[8][4];
        #pragma unroll
        for (int nt = 0; nt < 8; nt++)
            #pragma unroll
            for (int c = 0; c < 4; c++) s[nt][c] = 0.f;

        #pragma unroll
        for (int ks = 0; ks < 8; ks++) {
            #pragma unroll
            for (int nt = 0; nt < 8; nt++) {
                const float2 kv2 = *(const float2*)&KF[(((ks * 8 + nt) * 32 + lane) << 1)];
                mma_tf32(s[nt][0], s[nt][1], s[nt][2], s[nt][3],
                         qf[ks][0], qf[ks][1], qf[ks][2], qf[ks][3],
                         __float_as_uint(kv2.x), __float_as_uint(kv2.y));
            }
        }

        // ---- mask (skipped on fully-visible interior tiles) ----
        const bool interior = (kt < 2 * qt) & (allv != 0);
        if (!interior) {
            #pragma unroll
            for (int nt = 0; nt < 8; nt++) {
                const int lc0 = nt * 8 + 2 * tig;
                const int c0g = kv0 + lc0;
                const bool v0 = (msk[lc0] != 0);
                const bool v1 = (msk[lc0 + 1] != 0);
                if (!v0 | (c0g     > q_row0)) s[nt][0] = -1e30f;
                if (!v1 | (c0g + 1 > q_row0)) s[nt][1] = -1e30f;
                if (!v0 | (c0g     > q_row1)) s[nt][2] = -1e30f;
                if (!v1 | (c0g + 1 > q_row1)) s[nt][3] = -1e30f;
            }
        }

        // ---- online softmax ----
        float mx0 = -1e30f, mx1 = -1e30f;
        #pragma unroll
        for (int nt = 0; nt < 8; nt++) {
            mx0 = fmaxf(mx0, fmaxf(s[nt][0], s[nt][1]));
            mx1 = fmaxf(mx1, fmaxf(s[nt][2], s[nt][3]));
        }
        mx0 = fmaxf(mx0, __shfl_xor_sync(0xffffffffu, mx0, 1));
        mx0 = fmaxf(mx0, __shfl_xor_sync(0xffffffffu, mx0, 2));
        mx1 = fmaxf(mx1, __shfl_xor_sync(0xffffffffu, mx1, 1));
        mx1 = fmaxf(mx1, __shfl_xor_sync(0xffffffffu, mx1, 2));

        const float mn0 = fmaxf(m0r, mx0);
        const float mn1 = fmaxf(m1r, mx1);
        const float cr0 = exp2f(m0r - mn0);
        const float cr1 = exp2f(m1r - mn1);
        l0 *= cr0;  l1 *= cr1;
        m0r = mn0;  m1r = mn1;
        #pragma unroll
        for (int nt = 0; nt < 8; nt++) {
            o[nt][0] *= cr0; o[nt][1] *= cr0;
            o[nt][2] *= cr1; o[nt][3] *= cr1;
        }

        // ---- p = exp2(s - m); store P slice (tf32) ----
        #pragma unroll
        for (int nt = 0; nt < 8; nt++) {
            const float p0 = exp2f(s[nt][0] - mn0);
            const float p1 = exp2f(s[nt][1] - mn0);
            const float p2 = exp2f(s[nt][2] - mn1);
            const float p3 = exp2f(s[nt][3] - mn1);
            l0 += p0 + p1;
            l1 += p2 + p3;
            const int col = nt * 8 + 2 * tig;
            float* pr0 = &Ps[(mw + grp    ) * PSTR + col];
            float* pr1 = &Ps[(mw + grp + 8) * PSTR + col];
            pr0[0] = f2tf32f(p0);
            pr0[1] = f2tf32f(p1);
            pr1[0] = f2tf32f(p2);
            pr1[1] = f2tf32f(p3);
        }
        __syncwarp();

        // ---- O += P @ V ----
        #pragma unroll
        for (int ks = 0; ks < 8; ks++) {
            const int k8 = ks * 8;
            uint32_t a0 = __float_as_uint(Ps[(mw + grp    ) * PSTR + k8 + tig    ]);
            uint32_t a1 = __float_as_uint(Ps[(mw + grp + 8) * PSTR + k8 + tig    ]);
            uint32_t a2 = __float_as_uint(Ps[(mw + grp    ) * PSTR + k8 + tig + 4]);
            uint32_t a3 = __float_as_uint(Ps[(mw + grp + 8) * PSTR + k8 + tig + 4]);
            #pragma unroll
            for (int nt = 0; nt < 8; nt++) {
                const uint32_t b0 = __float_as_uint(Vs[(k8 + tig    ) * VSTR + nt * 8 + grp]);
                const uint32_t b1 = __float_as_uint(Vs[(k8 + tig + 4) * VSTR + nt * 8 + grp]);
                mma_tf32(o[nt][0], o[nt][1], o[nt][2], o[nt][3],
                         a0, a1, a2, a3, b0, b1);
            }
        }
    }

    // ---- finalize ----
    l0 += __shfl_xor_sync(0xffffffffu, l0, 1);
    l0 += __shfl_xor_sync(0xffffffffu, l0, 2);
    l1 += __shfl_xor_sync(0xffffffffu, l1, 1);
    l1 += __shfl_xor_sync(0xffffffffu, l1, 2);
    const float inv0 = 1.f / l0;
    const float inv1 = 1.f / l1;

    float* o0 = Og + ((size_t)(b * SEQ + q_row0)) * EMB + h * HD;
    float* o1 = Og + ((size_t)(b * SEQ + q_row1)) * EMB + h * HD;
    #pragma unroll
    for (int nt = 0; nt < 8; nt++) {
        const int col = nt * 8 + 2 * tig;
        *(float2*)(o0 + col) = make_float2(o[nt][0] * inv0, o[nt][1] * inv0);
        *(float2*)(o1 + col) = make_float2(o[nt][2] * inv1, o[nt][3] * inv1);
    }
}

// ---------------- launch --------------------------------------------------------
extern "C" void kernel_launch(void* const* d_in, const int* in_sizes, int n_in,
                              void* d_out, int out_size)
{
    const float* x  = (const float*)d_in[0];
    const int*   am = (const int*)  d_in[1];
    const float* wq = (const float*)d_in[2];
    const float* wk = (const float*)d_in[3];
    const float* wv = (const float*)d_in[4];
    const float* wo = (const float*)d_in[5];
    float* out = (float*)d_out;

    float *pq, *pk, *pv, *pao;
    cudaGetSymbolAddress((void**)&pq,  g_q);
    cudaGetSymbolAddress((void**)&pk,  g_k);
    cudaGetSymbolAddress((void**)&pv,  g_v);
    cudaGetSymbolAddress((void**)&pao, g_ao);

    qkv_gemm<<<dim3(EMB / BN, MROWS / BM, 3), 256>>>(x, wq, wk, wv, pq, pk, pv);

    cudaFuncSetAttribute(flash_tc, cudaFuncAttributeMaxDynamicSharedMemorySize,
                         FLASH_SMEM_BYTES);
    flash_tc<<<dim3(BATCH * NH, SEQ / 128), 256, FLASH_SMEM_BYTES>>>(pq, pk, pv, am, pao);

    out_gemm<<<dim3(EMB / BN, MROWS / BM), 256>>>(pao, wo, out);
}

// round 9
// speedup vs baseline: 1.5450x; 1.5450x over previous
#include <cuda_runtime.h>
#include <stdint.h>

#define EMB   1024
#define NH    16
#define HD    64
#define BATCH 4
#define SEQ   2048
#define MROWS (BATCH*SEQ)   // 8192
#define KDIM  EMB           // 1024

// ---------------- scratch (static __device__, allocation-guard safe) ----------
__device__ float g_q [(size_t)BATCH*NH*SEQ*HD];   // [B,H,S,D]
__device__ float g_k [(size_t)BATCH*NH*SEQ*HD];
__device__ float g_v [(size_t)BATCH*NH*SEQ*HD];
__device__ float g_ao[(size_t)MROWS*EMB];         // attention out, [B,S,E]

// ---------------- TF32 / MMA / LDSM helpers ------------------------------------
__device__ __forceinline__ uint32_t f2tf32(float x) {
    uint32_t r;
    asm("cvt.rna.tf32.f32 %0, %1;" : "=r"(r) : "f"(x));
    return r;
}
__device__ __forceinline__ float f2tf32f(float x) {
    return __uint_as_float(f2tf32(x));
}

__device__ __forceinline__ void mma_tf32(float& d0, float& d1, float& d2, float& d3,
                                         uint32_t a0, uint32_t a1, uint32_t a2, uint32_t a3,
                                         uint32_t b0, uint32_t b1)
{
    asm volatile(
        "mma.sync.aligned.m16n8k8.row.col.f32.tf32.tf32.f32 "
        "{%0,%1,%2,%3}, {%4,%5,%6,%7}, {%8,%9}, {%0,%1,%2,%3};"
        : "+f"(d0), "+f"(d1), "+f"(d2), "+f"(d3)
        : "r"(a0), "r"(a1), "r"(a2), "r"(a3), "r"(b0), "r"(b1));
}

// ldmatrix on 32-bit (tf32) data viewed as b16 pairs.
// x4: lanes 0-7 -> r0 (rows 0-7, k 0-3), 8-15 -> r1 (rows 8-15, k 0-3),
//     16-23 -> r2 (rows 0-7, k 4-7), 24-31 -> r3 (rows 8-15, k 4-7)
__device__ __forceinline__ void ldsm_x4(uint32_t* r, uint32_t addr) {
    asm volatile("ldmatrix.sync.aligned.m8n8.x4.shared.b16 {%0,%1,%2,%3}, [%4];"
                 : "=r"(r[0]), "=r"(r[1]), "=r"(r[2]), "=r"(r[3]) : "r"(addr));
}
__device__ __forceinline__ void ldsm_x2(uint32_t* r, uint32_t addr) {
    asm volatile("ldmatrix.sync.aligned.m8n8.x2.shared.b16 {%0,%1}, [%2];"
                 : "=r"(r[0]), "=r"(r[1]) : "r"(addr));
}

// ---------------- TF32 tensor-core GEMM (double-buffered, ldmatrix) ------------
// C[M,N] = A[M,K] @ W[N,K]^T.  Block 128x128x32, 8 warps (2x4), warp tile 64x32.
// Row-major smem tiles (stride 36): STS.128 staging conflict-free,
// ldmatrix rows land (4*row+col)%32 -> conflict-free fragment loads.
#define BM 128
#define BN 128
#define BK 32
#define GST 36
#define BUF_FLOATS (2*BM*GST)            // As + Ws = 9216 floats per buffer
#define GSMEM_BYTES (2*BUF_FLOATS*4)     // 73728

template<bool SPLIT>
__device__ __forceinline__ void gemm_body(const float* __restrict__ A,
                                          const float* __restrict__ W,
                                          float* __restrict__ C,
                                          float* __restrict__ sm)
{
    const int tid    = threadIdx.x;
    const int lane   = tid & 31;
    const int warp   = tid >> 5;
    const int warp_m = warp >> 2;           // 0..1
    const int warp_n = warp & 3;            // 0..3
    const int m0     = blockIdx.y * BM;
    const int n0     = blockIdx.x * BN;
    const int mw     = warp_m * 64;
    const int nw     = warp_n * 32;

    const uint32_t sbase = (uint32_t)__cvta_generic_to_shared(sm);

    // per-lane ldmatrix byte offsets within a buffer
    uint32_t aoff[4], boff[4];
    #pragma unroll
    for (int mi = 0; mi < 4; mi++)
        aoff[mi] = (uint32_t)(((mw + mi * 16 + (lane & 15)) * GST + 4 * (lane >> 4)) * 4);
    #pragma unroll
    for (int ni = 0; ni < 4; ni++)
        boff[ni] = (uint32_t)(((nw + ni * 8 + (lane & 7)) * GST + 4 * ((lane >> 3) & 1)
                               + BM * GST) * 4);

    const int srow = tid >> 3;              // 0..31 (+32p)
    const int scol = (tid & 7) * 4;         // 0,4,..,28

    float acc[4][4][4];
    #pragma unroll
    for (int i = 0; i < 4; i++)
        #pragma unroll
        for (int j = 0; j < 4; j++)
            #pragma unroll
            for (int c = 0; c < 4; c++) acc[i][j][c] = 0.f;

    float4 sa[4], sw[4];
    // slab 0 -> regs
    #pragma unroll
    for (int p = 0; p < 4; p++) {
        const int row = srow + p * 32;
        sa[p] = *(const float4*)(A + (size_t)(m0 + row) * KDIM + scol);
        sw[p] = *(const float4*)(W + (size_t)(n0 + row) * KDIM + scol);
    }
    // stage slab 0 -> buf0
    #pragma unroll
    for (int p = 0; p < 4; p++) {
        const int row = srow + p * 32;
        float* ap = sm + row * GST + scol;
        ap[0] = f2tf32f(sa[p].x); ap[1] = f2tf32f(sa[p].y);
        ap[2] = f2tf32f(sa[p].z); ap[3] = f2tf32f(sa[p].w);
        float* wp = sm + BM * GST + row * GST + scol;
        wp[0] = f2tf32f(sw[p].x); wp[1] = f2tf32f(sw[p].y);
        wp[2] = f2tf32f(sw[p].z); wp[3] = f2tf32f(sw[p].w);
    }
    // slab 1 -> regs
    #pragma unroll
    for (int p = 0; p < 4; p++) {
        const int row = srow + p * 32;
        sa[p] = *(const float4*)(A + (size_t)(m0 + row) * KDIM + BK + scol);
        sw[p] = *(const float4*)(W + (size_t)(n0 + row) * KDIM + BK + scol);
    }
    __syncthreads();

    const int NIT = KDIM / BK;   // 32
    for (int it = 0; it < NIT; it++) {
        // stage regs (slab it+1) into the idle buffer; overlaps compute below
        if (it < NIT - 1) {
            float* dst = sm + ((it + 1) & 1) * BUF_FLOATS;
            #pragma unroll
            for (int p = 0; p < 4; p++) {
                const int row = srow + p * 32;
                float* ap = dst + row * GST + scol;
                ap[0] = f2tf32f(sa[p].x); ap[1] = f2tf32f(sa[p].y);
                ap[2] = f2tf32f(sa[p].z); ap[3] = f2tf32f(sa[p].w);
                float* wp = dst + BM * GST + row * GST + scol;
                wp[0] = f2tf32f(sw[p].x); wp[1] = f2tf32f(sw[p].y);
                wp[2] = f2tf32f(sw[p].z); wp[3] = f2tf32f(sw[p].w);
            }
        }
        // prefetch slab it+2
        if (it < NIT - 2) {
            const int kk = (it + 2) * BK + scol;
            #pragma unroll
            for (int p = 0; p < 4; p++) {
                const int row = srow + p * 32;
                sa[p] = *(const float4*)(A + (size_t)(m0 + row) * KDIM + kk);
                sw[p] = *(const float4*)(W + (size_t)(n0 + row) * KDIM + kk);
            }
        }
        // compute from current buffer
        const uint32_t bufo = (uint32_t)((it & 1) * BUF_FLOATS * 4);
        #pragma unroll
        for (int kb = 0; kb < 4; kb++) {
            const uint32_t ko = bufo + kb * 32;   // 8 floats = 32 bytes per k-block
            uint32_t af[4][4];
            #pragma unroll
            for (int mi = 0; mi < 4; mi++)
                ldsm_x4(af[mi], sbase + ko + aoff[mi]);
            uint32_t bf[4][2];
            #pragma unroll
            for (int ni = 0; ni < 4; ni++)
                ldsm_x2(bf[ni], sbase + ko + boff[ni]);
            #pragma unroll
            for (int mi = 0; mi < 4; mi++)
                #pragma unroll
                for (int ni = 0; ni < 4; ni++)
                    mma_tf32(acc[mi][ni][0], acc[mi][ni][1], acc[mi][ni][2], acc[mi][ni][3],
                             af[mi][0], af[mi][1], af[mi][2], af[mi][3],
                             bf[ni][0], bf[ni][1]);
        }
        __syncthreads();
    }

    // ---- epilogue ----
    const int grp = lane >> 2;
    const int tig = lane & 3;
    #pragma unroll
    for (int mi = 0; mi < 4; mi++) {
        #pragma unroll
        for (int ni = 0; ni < 4; ni++) {
            const int row = m0 + mw + mi * 16 + grp;
            const int col = n0 + nw + ni * 8 + 2 * tig;
            #pragma unroll
            for (int half = 0; half < 2; half++) {
                const int m = row + half * 8;
                const float v0 = acc[mi][ni][half * 2 + 0];
                const float v1 = acc[mi][ni][half * 2 + 1];
                size_t idx;
                if (SPLIT) {   // [B,H,S,D]
                    const int b = m >> 11, s = m & 2047, h = col >> 6, d = col & 63;
                    idx = ((size_t)(b * NH + h) * SEQ + s) * HD + d;
                } else {
                    idx = (size_t)m * EMB + col;
                }
                *(float2*)(C + idx) = make_float2(v0, v1);
            }
        }
    }
}

// fused QKV: gridDim.z = 3 selects weight/output
__global__ void __launch_bounds__(256)
qkv_gemm(const float* __restrict__ x,
         const float* __restrict__ wq, const float* __restrict__ wk,
         const float* __restrict__ wv,
         float* __restrict__ pq, float* __restrict__ pk, float* __restrict__ pv)
{
    extern __shared__ __align__(16) float smg[];
    const int z = blockIdx.z;
    const float* W = (z == 0) ? wq : (z == 1) ? wk : wv;
    float*       C = (z == 0) ? pq : (z == 1) ? pk : pv;
    gemm_body<true>(x, W, C, smg);
}

__global__ void __launch_bounds__(256)
out_gemm(const float* __restrict__ A, const float* __restrict__ W,
         float* __restrict__ C)
{
    extern __shared__ __align__(16) float smg[];
    gemm_body<false>(A, W, C, smg);
}

// ---------------- tensor-core causal flash attention ---------------------------
// CTA: 128 q-rows of one (b,h). 8 warps x 16 q-rows. KV tiles of 64.
// Row-major smem (K/P stride 68, V stride 72); Q/K/P fragments via ldmatrix.
#define KST 68
#define VSTR 72
#define FLASH_SMEM_FLOATS (64*KST + 64*VSTR + 128*KST)
#define FLASH_SMEM_BYTES  (FLASH_SMEM_FLOATS*4 + 64*4)

__global__ void __launch_bounds__(256)
flash_tc(const float* __restrict__ Qg, const float* __restrict__ Kg,
         const float* __restrict__ Vg, const int* __restrict__ maskg,
         float* __restrict__ Og)
{
    extern __shared__ __align__(16) float sm[];
    float* Ks = sm;                    // [64][KST]
    float* Vs = Ks + 64 * KST;         // [64][VSTR]
    float* Ps = Vs + 64 * VSTR;        // [128][KST]  (Q staging, then P)
    int*   msk = (int*)(Ps + 128 * KST);

    const int bh   = blockIdx.x;
    const int b    = bh >> 4;
    const int h    = bh & 15;
    const int qt   = gridDim.y - 1 - blockIdx.y;   // heavy tiles first
    const int q0   = qt * 128;
    const int tid  = threadIdx.x;
    const int lane = tid & 31;
    const int warp = tid >> 5;
    const int grp  = lane >> 2;
    const int tig  = lane & 3;
    const int mw   = warp * 16;

    const uint32_t sbK = (uint32_t)__cvta_generic_to_shared(Ks);
    const uint32_t sbP = (uint32_t)__cvta_generic_to_shared(Ps);
    // ldmatrix per-lane offsets
    const uint32_t paoff = (uint32_t)(((mw + (lane & 15)) * KST + 4 * (lane >> 4)) * 4);
    const uint32_t kboff = (uint32_t)((((lane & 7)) * KST + 4 * ((lane >> 3) & 1)) * 4);

    const float qscale = 0.125f * 1.44269504088896f;  // 1/sqrt(64) * log2(e)

    // ---- stage Q tile [128 x 64] (scaled, tf32) into Ps ----
    #pragma unroll
    for (int p = 0; p < 8; p++) {
        const int idx = tid + p * 256;
        const int row = idx >> 4;
        const int col = (idx & 15) * 4;
        float4 t = *(const float4*)(Qg + ((size_t)bh * SEQ + q0 + row) * HD + col);
        float* dp = &Ps[row * KST + col];
        dp[0] = f2tf32f(t.x * qscale);
        dp[1] = f2tf32f(t.y * qscale);
        dp[2] = f2tf32f(t.z * qscale);
        dp[3] = f2tf32f(t.w * qscale);
    }
    __syncthreads();

    uint32_t qf[8][4];
    #pragma unroll
    for (int ks = 0; ks < 8; ks++)
        ldsm_x4(qf[ks], sbP + paoff + ks * 32);

    float o[8][4];
    #pragma unroll
    for (int nt = 0; nt < 8; nt++)
        #pragma unroll
        for (int c = 0; c < 4; c++) o[nt][c] = 0.f;
    float m0r = -1e30f, m1r = -1e30f, l0 = 0.f, l1 = 0.f;

    const int q_row0 = q0 + mw + grp;
    const int q_row1 = q_row0 + 8;
    const int* mrow  = maskg + b * SEQ;
    const int  ntile = 2 * qt + 2;

    for (int kt = 0; kt < ntile; kt++) {
        const int kv0 = kt * 64;
        __syncthreads();   // previous tile's Ks/Vs (and P) reads complete

        // ---- load K,V tiles (tf32) + mask ----
        #pragma unroll
        for (int p = 0; p < 4; p++) {
            const int idx = tid + p * 256;
            const int row = idx >> 4;
            const int col = (idx & 15) * 4;
            float4 tk = *(const float4*)(Kg + ((size_t)bh * SEQ + kv0 + row) * HD + col);
            float* kp = &Ks[row * KST + col];
            kp[0] = f2tf32f(tk.x); kp[1] = f2tf32f(tk.y);
            kp[2] = f2tf32f(tk.z); kp[3] = f2tf32f(tk.w);
            float4 tv = *(const float4*)(Vg + ((size_t)bh * SEQ + kv0 + row) * HD + col);
            float* vp = &Vs[row * VSTR + col];
            vp[0] = f2tf32f(tv.x); vp[1] = f2tf32f(tv.y);
            vp[2] = f2tf32f(tv.z); vp[3] = f2tf32f(tv.w);
        }
        int mv = 1;
        if (tid < 64) { mv = mrow[kv0 + tid]; msk[tid] = mv; }
        const int allv = __syncthreads_and(mv != 0);   // barrier + all-reduce

        // ---- S = Q @ K^T ----
        float s[8][4];
        #pragma unroll
        for (int nt = 0; nt < 8; nt++)
            #pragma unroll
            for (int c = 0; c < 4; c++) s[nt][c] = 0.f;

        #pragma unroll
        for (int ks = 0; ks < 8; ks++) {
            #pragma unroll
            for (int nt = 0; nt < 8; nt++) {
                uint32_t bf[2];
                ldsm_x2(bf, sbK + kboff + (uint32_t)(nt * (8 * KST * 4)) + ks * 32);
                mma_tf32(s[nt][0], s[nt][1], s[nt][2], s[nt][3],
                         qf[ks][0], qf[ks][1], qf[ks][2], qf[ks][3],
                         bf[0], bf[1]);
            }
        }

        // ---- mask (skipped on fully-visible interior tiles) ----
        const bool interior = (kt < 2 * qt) & (allv != 0);
        if (!interior) {
            #pragma unroll
            for (int nt = 0; nt < 8; nt++) {
                const int lc0 = nt * 8 + 2 * tig;
                const int c0g = kv0 + lc0;
                const bool v0 = (msk[lc0] != 0);
                const bool v1 = (msk[lc0 + 1] != 0);
                if (!v0 | (c0g     > q_row0)) s[nt][0] = -1e30f;
                if (!v1 | (c0g + 1 > q_row0)) s[nt][1] = -1e30f;
                if (!v0 | (c0g     > q_row1)) s[nt][2] = -1e30f;
                if (!v1 | (c0g + 1 > q_row1)) s[nt][3] = -1e30f;
            }
        }

        // ---- online softmax ----
        float mx0 = -1e30f, mx1 = -1e30f;
        #pragma unroll
        for (int nt = 0; nt < 8; nt++) {
            mx0 = fmaxf(mx0, fmaxf(s[nt][0], s[nt][1]));
            mx1 = fmaxf(mx1, fmaxf(s[nt][2], s[nt][3]));
        }
        mx0 = fmaxf(mx0, __shfl_xor_sync(0xffffffffu, mx0, 1));
        mx0 = fmaxf(mx0, __shfl_xor_sync(0xffffffffu, mx0, 2));
        mx1 = fmaxf(mx1, __shfl_xor_sync(0xffffffffu, mx1, 1));
        mx1 = fmaxf(mx1, __shfl_xor_sync(0xffffffffu, mx1, 2));

        const float mn0 = fmaxf(m0r, mx0);
        const float mn1 = fmaxf(m1r, mx1);
        const float cr0 = exp2f(m0r - mn0);
        const float cr1 = exp2f(m1r - mn1);
        l0 *= cr0;  l1 *= cr1;
        m0r = mn0;  m1r = mn1;
        #pragma unroll
        for (int nt = 0; nt < 8; nt++) {
            o[nt][0] *= cr0; o[nt][1] *= cr0;
            o[nt][2] *= cr1; o[nt][3] *= cr1;
        }

        // ---- p = exp2(s - m); store P slice (tf32) ----
        #pragma unroll
        for (int nt = 0; nt < 8; nt++) {
            const float p0 = exp2f(s[nt][0] - mn0);
            const float p1 = exp2f(s[nt][1] - mn0);
            const float p2 = exp2f(s[nt][2] - mn1);
            const float p3 = exp2f(s[nt][3] - mn1);
            l0 += p0 + p1;
            l1 += p2 + p3;
            const int col = nt * 8 + 2 * tig;
            float* pr0 = &Ps[(mw + grp    ) * KST + col];
            float* pr1 = &Ps[(mw + grp + 8) * KST + col];
            pr0[0] = f2tf32f(p0);
            pr0[1] = f2tf32f(p1);
            pr1[0] = f2tf32f(p2);
            pr1[1] = f2tf32f(p3);
        }
        __syncwarp();

        // ---- O += P @ V ----
        #pragma unroll
        for (int ks = 0; ks < 8; ks++) {
            const int k8 = ks * 8;
            uint32_t a[4];
            ldsm_x4(a, sbP + paoff + ks * 32);
            #pragma unroll
            for (int nt = 0; nt < 8; nt++) {
                const uint32_t b0 = __float_as_uint(Vs[(k8 + tig    ) * VSTR + nt * 8 + grp]);
                const uint32_t b1 = __float_as_uint(Vs[(k8 + tig + 4) * VSTR + nt * 8 + grp]);
                mma_tf32(o[nt][0], o[nt][1], o[nt][2], o[nt][3],
                         a[0], a[1], a[2], a[3], b0, b1);
            }
        }
    }

    // ---- finalize ----
    l0 += __shfl_xor_sync(0xffffffffu, l0, 1);
    l0 += __shfl_xor_sync(0xffffffffu, l0, 2);
    l1 += __shfl_xor_sync(0xffffffffu, l1, 1);
    l1 += __shfl_xor_sync(0xffffffffu, l1, 2);
    const float inv0 = 1.f / l0;
    const float inv1 = 1.f / l1;

    float* o0 = Og + ((size_t)(b * SEQ + q_row0)) * EMB + h * HD;
    float* o1 = Og + ((size_t)(b * SEQ + q_row1)) * EMB + h * HD;
    #pragma unroll
    for (int nt = 0; nt < 8; nt++) {
        const int col = nt * 8 + 2 * tig;
        *(float2*)(o0 + col) = make_float2(o[nt][0] * inv0, o[nt][1] * inv0);
        *(float2*)(o1 + col) = make_float2(o[nt][2] * inv1, o[nt][3] * inv1);
    }
}

// ---------------- launch --------------------------------------------------------
extern "C" void kernel_launch(void* const* d_in, const int* in_sizes, int n_in,
                              void* d_out, int out_size)
{
    const float* x  = (const float*)d_in[0];
    const int*   am = (const int*)  d_in[1];
    const float* wq = (const float*)d_in[2];
    const float* wk = (const float*)d_in[3];
    const float* wv = (const float*)d_in[4];
    const float* wo = (const float*)d_in[5];
    float* out = (float*)d_out;

    float *pq, *pk, *pv, *pao;
    cudaGetSymbolAddress((void**)&pq,  g_q);
    cudaGetSymbolAddress((void**)&pk,  g_k);
    cudaGetSymbolAddress((void**)&pv,  g_v);
    cudaGetSymbolAddress((void**)&pao, g_ao);

    // unconditional attribute sets (no static guards; host-side, capture-safe)
    cudaFuncSetAttribute(qkv_gemm, cudaFuncAttributeMaxDynamicSharedMemorySize, GSMEM_BYTES);
    cudaFuncSetAttribute(out_gemm, cudaFuncAttributeMaxDynamicSharedMemorySize, GSMEM_BYTES);
    cudaFuncSetAttribute(flash_tc, cudaFuncAttributeMaxDynamicSharedMemorySize, FLASH_SMEM_BYTES);

    qkv_gemm<<<dim3(EMB / BN, MROWS / BM, 3), 256, GSMEM_BYTES>>>(x, wq, wk, wv, pq, pk, pv);

    flash_tc<<<dim3(BATCH * NH, SEQ / 128), 256, FLASH_SMEM_BYTES>>>(pq, pk, pv, am, pao);

    out_gemm<<<dim3(EMB / BN, MROWS / BM), 256, GSMEM_BYTES>>>(pao, wo, out);
}